// round 6
// baseline (speedup 1.0000x reference)
#include <cuda_runtime.h>
#include <math.h>

// e^{u.v} = sum_{a+b+c<=7} u^(a,b,c) v^(a,b,c) / (a!b!c!)   (|u.v|<=1)
// Z_i = sum_f c_f mono_f(u_i) M_f ; W_i = sum_f |f| c_f mono_f(u_i) M_f
// mean H = (1/N) sum_i (log Z_i - W_i/Z_i) - N*1e-8
// K1: moments + last-block fold -> g_MZW.  K2: entropy + last-block mean.

#define KDEG   7
#define NF     120          // C(10,3)
#define NFP    128          // 4*32
#define NGRP   4
#define TPB    128
#define MAXBLK 128

__device__ float    g_Mp[MAXBLK * NFP];  // per-block raw moment partials [blk][feat]
__device__ float2   g_MZW[NFP];          // (c_f*M_f, |f|*c_f*M_f)
__device__ float    g_Hp[MAXBLK];
__device__ unsigned g_t1;                // zero-init; reset by last block each run
__device__ unsigned g_t2;

__device__ __forceinline__ void load_unit(const float* __restrict__ vel, int i,
                                          float& x, float& y, float& z) {
    x = vel[3 * i + 0];
    y = vel[3 * i + 1];
    z = vel[3 * i + 2];
    float nrm = sqrtf(x * x + y * y + z * z);
    float inv = 1.0f / (nrm + 1e-6f);
    x *= inv; y *= inv; z *= inv;
}

// ---------------- K1: per-block moments + last-block fold ----------------
__global__ void __launch_bounds__(TPB)
moments_kernel(const float* __restrict__ vel, int N, int nblk) {
    __shared__ float s4[4][NFP];
    __shared__ int   islast;
    int tid  = threadIdx.x;
    int lane = tid & 31;
    int warp = tid >> 5;

    int i = blockIdx.x * TPB + tid;        // grid covers N exactly (or masks)
    float x = 0.f, y = 0.f, z = 0.f, w = 0.f;
    if (i < N) { load_unit(vel, i, x, y, z); w = 1.0f; }

    float px[KDEG + 1], py[KDEG + 1], pz[KDEG + 1];
    px[0] = w; py[0] = 1.0f; pz[0] = 1.0f;          // w masks inactive lanes
#pragma unroll
    for (int d = 1; d <= KDEG; d++) {
        px[d] = px[d - 1] * x;
        py[d] = py[d - 1] * y;
        pz[d] = pz[d - 1] * z;
    }

    // materialize all monomials, grouped for 4 interleaved butterflies
    float v[NGRP][32];
    {
        int idx = 0;
#pragma unroll
        for (int a = 0; a <= KDEG; a++) {
#pragma unroll
            for (int b = 0; b <= KDEG - a; b++) {
                float xy = px[a] * py[b];
#pragma unroll
                for (int c = 0; c <= KDEG - a - b; c++) {
                    v[idx >> 5][idx & 31] = xy * pz[c];
                    idx++;
                }
            }
        }
#pragma unroll
        for (int k = 24; k < 32; k++) v[3][k] = 0.f;   // pad 120 -> 128
    }

    // 4 butterflies in lock-step: 4x ILP at every step
#pragma unroll
    for (int m = 16; m >= 1; m >>= 1) {
        bool hi = (lane & m) != 0;
#pragma unroll
        for (int g = 0; g < NGRP; g++) {
#pragma unroll
            for (int k = 0; k < 16; k++) {
                if (k < m) {
                    float keep = hi ? v[g][k + m] : v[g][k];
                    float send = hi ? v[g][k] : v[g][k + m];
                    v[g][k] = keep + __shfl_xor_sync(0xffffffffu, send, m);
                }
            }
        }
    }

#pragma unroll
    for (int g = 0; g < NGRP; g++) s4[warp][g * 32 + lane] = v[g][0];
    __syncthreads();
    g_Mp[blockIdx.x * NFP + tid] = s4[0][tid] + s4[1][tid] + s4[2][tid] + s4[3][tid];

    // ---- last-block fold: coalesced global reduce + coefficient folding ----
    __threadfence();
    if (tid == 0) islast = (atomicAdd(&g_t1, 1u) == (unsigned)(nblk - 1));
    __syncthreads();
    if (!islast) return;
    __threadfence();

    float m = 0.f;
#pragma unroll 16
    for (int b = 0; b < nblk; b++) m += g_Mp[b * NFP + tid];   // coalesced per b

    float cf = 0.f, deg = 0.f;
    if (tid < NF) {
        int rem = tid, a = 0, b = 0;
        for (a = 0; a <= KDEG; a++) {
            int cnt = (KDEG + 1 - a) * (KDEG + 2 - a) / 2;
            if (rem < cnt) break;
            rem -= cnt;
        }
        for (b = 0; b <= KDEG - a; b++) {
            int cnt = KDEG + 1 - a - b;
            if (rem < cnt) break;
            rem -= cnt;
        }
        int c = rem;
        float fa = 1.f, fb = 1.f, fc = 1.f;
        for (int t = 2; t <= a; t++) fa *= (float)t;
        for (int t = 2; t <= b; t++) fb *= (float)t;
        for (int t = 2; t <= c; t++) fc *= (float)t;
        cf  = 1.0f / (fa * fb * fc);
        deg = (float)(a + b + c);
    }
    g_MZW[tid] = make_float2(cf * m, cf * deg * m);
    if (tid == 0) g_t1 = 0u;       // reset for next graph replay
}

// ---------------- K2: per-point entropy + last-block mean ----------------
__global__ void __launch_bounds__(TPB)
entropy_kernel(const float* __restrict__ vel, float* __restrict__ out,
               int N, int nblk) {
    __shared__ float2 sM[NFP];
    __shared__ float  rs[4];
    __shared__ int    islast;
    int tid  = threadIdx.x;
    int lane = tid & 31;
    int warp = tid >> 5;

    sM[tid] = g_MZW[tid];
    __syncthreads();
    const unsigned long long* sM64 = reinterpret_cast<const unsigned long long*>(sM);

    int i = blockIdx.x * TPB + tid;
    float H = 0.f;
    if (i < N) {
        float x, y, z;
        load_unit(vel, i, x, y, z);

        float px[KDEG + 1], py[KDEG + 1], pz[KDEG + 1];
        px[0] = 1.0f; py[0] = 1.0f; pz[0] = 1.0f;
#pragma unroll
        for (int d = 1; d <= KDEG; d++) {
            px[d] = px[d - 1] * x;
            py[d] = py[d - 1] * y;
            pz[d] = pz[d - 1] * z;
        }

        // four packed (Z,W) accumulators -> quarter the FMA RAW chain
        unsigned long long acc[4] = {0ull, 0ull, 0ull, 0ull};
        int idx = 0;
#pragma unroll
        for (int a = 0; a <= KDEG; a++) {
#pragma unroll
            for (int b = 0; b <= KDEG - a; b++) {
                float xy = px[a] * py[b];
#pragma unroll
                for (int c = 0; c <= KDEG - a - b; c++) {
                    float mono = xy * pz[c];
                    unsigned int mu = __float_as_uint(mono);
                    unsigned long long mm;
                    asm("mov.b64 %0, {%1, %1};" : "=l"(mm) : "r"(mu));
                    int s = idx & 3;
                    asm("fma.rn.f32x2 %0, %1, %2, %3;"
                        : "=l"(acc[s]) : "l"(mm), "l"(sM64[idx]), "l"(acc[s]));
                    idx++;
                }
            }
        }
        float Z = 0.f, W = 0.f;
#pragma unroll
        for (int s = 0; s < 4; s++) {
            unsigned int zu, wu;
            asm("mov.b64 {%0, %1}, %2;" : "=r"(zu), "=r"(wu) : "l"(acc[s]));
            Z += __uint_as_float(zu);
            W += __uint_as_float(wu);
        }
        H = logf(Z) - W / Z;
    }

    H += __shfl_xor_sync(0xffffffffu, H, 16);
    H += __shfl_xor_sync(0xffffffffu, H, 8);
    H += __shfl_xor_sync(0xffffffffu, H, 4);
    H += __shfl_xor_sync(0xffffffffu, H, 2);
    H += __shfl_xor_sync(0xffffffffu, H, 1);
    if (lane == 0) rs[warp] = H;
    __syncthreads();
    if (tid == 0) g_Hp[blockIdx.x] = rs[0] + rs[1] + rs[2] + rs[3];

    // ---- last-block mean ----
    __threadfence();
    if (tid == 0) islast = (atomicAdd(&g_t2, 1u) == (unsigned)(nblk - 1));
    __syncthreads();
    if (!islast) return;
    __threadfence();

    float a = 0.f;
    for (int b = tid; b < nblk; b += TPB) a += g_Hp[b];
    a += __shfl_xor_sync(0xffffffffu, a, 16);
    a += __shfl_xor_sync(0xffffffffu, a, 8);
    a += __shfl_xor_sync(0xffffffffu, a, 4);
    a += __shfl_xor_sync(0xffffffffu, a, 2);
    a += __shfl_xor_sync(0xffffffffu, a, 1);
    if (lane == 0) rs[warp] = a;
    __syncthreads();
    if (tid == 0) {
        out[0] = (rs[0] + rs[1] + rs[2] + rs[3]) / (float)N - (float)N * 1e-8f;
        g_t2 = 0u;               // reset for next graph replay
    }
}

extern "C" void kernel_launch(void* const* d_in, const int* in_sizes, int n_in,
                              void* d_out, int out_size) {
    const float* vel = (const float*)d_in[0];   // velocities (N,3); positions unused
    int N = in_sizes[0] / 3;
    int nblk = (N + TPB - 1) / TPB;
    if (nblk > MAXBLK) nblk = MAXBLK;
    if (nblk < 1) nblk = 1;

    moments_kernel<<<nblk, TPB>>>(vel, N, nblk);
    entropy_kernel<<<nblk, TPB>>>(vel, (float*)d_out, N, nblk);
}

// round 7
// speedup vs baseline: 1.1604x; 1.1604x over previous
#include <cuda_runtime.h>
#include <math.h>

// e^{u.v} = sum_{a+b+c<=6} u^(a,b,c) v^(a,b,c) / (a!b!c!)   (|u.v|<=1)
//   Z tail 2.3e-4, W tail 1.5e-3 -> H rel err ~1e-4 << 1e-3
// Z_i = sum_f c_f mono_f(u_i) M_f ; W_i = sum_f |f| c_f mono_f(u_i) M_f
// mean H = (1/N) sum_i (log Z_i - W_i/Z_i) - N*1e-8

#define KDEG   6
#define NF     84           // C(9,3)
#define NFP    96           // 3*32
#define NGRP   3
#define TPB    128
#define MAXBLK 128

__device__ float    g_Mp[MAXBLK * NFP];  // per-block raw moment partials [blk][feat]
__device__ float2   g_MZW[NFP];          // (c_f*M_f, |f|*c_f*M_f)
__device__ float    g_Hp[MAXBLK];
__device__ unsigned g_t2;                // zero-init; reset by last block each run

__device__ __forceinline__ void load_unit(const float* __restrict__ vel, int i,
                                          float& x, float& y, float& z) {
    x = vel[3 * i + 0];
    y = vel[3 * i + 1];
    z = vel[3 * i + 2];
    float nrm = sqrtf(x * x + y * y + z * z);
    float inv = 1.0f / (nrm + 1e-6f);
    x *= inv; y *= inv; z *= inv;
}

// Butterfly compaction: 32 lane-local values -> lane l holds warp-sum of value l.
__device__ __forceinline__ float bfly32(float (&v)[32], int lane) {
#pragma unroll
    for (int m = 16; m >= 1; m >>= 1) {
        bool hi = (lane & m) != 0;
#pragma unroll
        for (int k = 0; k < 16; k++) {
            if (k < m) {
                float keep = hi ? v[k + m] : v[k];
                float send = hi ? v[k] : v[k + m];
                v[k] = keep + __shfl_xor_sync(0xffffffffu, send, m);
            }
        }
    }
    return v[0];
}

// ---------------- K1: per-block raw moments (R5 structure, KDEG=6) ----------------
__global__ void __launch_bounds__(TPB)
moments_kernel(const float* __restrict__ vel, int N, int nblk) {
    __shared__ float s4[4][NFP];
    int tid  = threadIdx.x;
    int lane = tid & 31;
    int warp = tid >> 5;

    int i = blockIdx.x * TPB + tid;
    float x = 0.f, y = 0.f, z = 0.f, w = 0.f;
    if (i < N) { load_unit(vel, i, x, y, z); w = 1.0f; }

    float px[KDEG + 1], py[KDEG + 1], pz[KDEG + 1];
    px[0] = w; py[0] = 1.0f; pz[0] = 1.0f;          // w masks inactive lanes
#pragma unroll
    for (int d = 1; d <= KDEG; d++) {
        px[d] = px[d - 1] * x;
        py[d] = py[d - 1] * y;
        pz[d] = pz[d - 1] * z;
    }

    float v[32];
    float acc[NGRP];
    int idx = 0;
#pragma unroll
    for (int a = 0; a <= KDEG; a++) {
#pragma unroll
        for (int b = 0; b <= KDEG - a; b++) {
            float xy = px[a] * py[b];
#pragma unroll
            for (int c = 0; c <= KDEG - a - b; c++) {
                v[idx & 31] = xy * pz[c];
                if ((idx & 31) == 31) acc[idx >> 5] = bfly32(v, lane);
                idx++;
            }
        }
    }
    // idx == 84: pad group 2 (indices 20..31)
#pragma unroll
    for (int k = 20; k < 32; k++) v[k] = 0.f;
    acc[2] = bfly32(v, lane);

#pragma unroll
    for (int g = 0; g < NGRP; g++) s4[warp][g * 32 + lane] = acc[g];
    __syncthreads();
    if (tid < NFP)
        g_Mp[blockIdx.x * NFP + tid] = s4[0][tid] + s4[1][tid] + s4[2][tid] + s4[3][tid];
}

// ---------------- K2: warp-per-feature reduce + coefficient folding ----------------
__global__ void __launch_bounds__(256)
reduce_kernel(int nblk) {
    int f    = (blockIdx.x * blockDim.x + threadIdx.x) >> 5;
    int lane = threadIdx.x & 31;
    if (f >= NFP) return;

    float acc = 0.f;
    for (int b = lane; b < nblk; b += 32) acc += g_Mp[b * NFP + f];
    acc += __shfl_xor_sync(0xffffffffu, acc, 16);
    acc += __shfl_xor_sync(0xffffffffu, acc, 8);
    acc += __shfl_xor_sync(0xffffffffu, acc, 4);
    acc += __shfl_xor_sync(0xffffffffu, acc, 2);
    acc += __shfl_xor_sync(0xffffffffu, acc, 1);

    if (lane == 0) {
        float cf = 0.f, deg = 0.f;
        if (f < NF) {
            int rem = f, a = 0, b = 0;
            for (a = 0; a <= KDEG; a++) {
                int cnt = (KDEG + 1 - a) * (KDEG + 2 - a) / 2;
                if (rem < cnt) break;
                rem -= cnt;
            }
            for (b = 0; b <= KDEG - a; b++) {
                int cnt = KDEG + 1 - a - b;
                if (rem < cnt) break;
                rem -= cnt;
            }
            int c = rem;
            float fa = 1.f, fb = 1.f, fc = 1.f;
            for (int t = 2; t <= a; t++) fa *= (float)t;
            for (int t = 2; t <= b; t++) fb *= (float)t;
            for (int t = 2; t <= c; t++) fc *= (float)t;
            cf  = 1.0f / (fa * fb * fc);
            deg = (float)(a + b + c);
        }
        g_MZW[f] = make_float2(cf * acc, cf * deg * acc);
    }
}

// templated quarter-of-features accumulator: SUB is compile-time, branch is
// uniform per warp -> no divergence, each thread does ~21 LDS + 21 FMA2
template <int SUB>
__device__ __forceinline__ void accum_zw(const unsigned long long* __restrict__ sM64,
                                         const float* px, const float* py,
                                         const float* pz, float& Z, float& W) {
    unsigned long long accA = 0ull, accB = 0ull;
    int idx = 0, cnt = 0;
#pragma unroll
    for (int a = 0; a <= KDEG; a++) {
#pragma unroll
        for (int b = 0; b <= KDEG - a; b++) {
            float xy = px[a] * py[b];
#pragma unroll
            for (int c = 0; c <= KDEG - a - b; c++) {
                if ((idx & 3) == SUB) {
                    float mono = xy * pz[c];
                    unsigned int mu = __float_as_uint(mono);
                    unsigned long long mm;
                    asm("mov.b64 %0, {%1, %1};" : "=l"(mm) : "r"(mu));
                    if (cnt & 1) {
                        asm("fma.rn.f32x2 %0, %1, %2, %3;"
                            : "=l"(accB) : "l"(mm), "l"(sM64[idx]), "l"(accB));
                    } else {
                        asm("fma.rn.f32x2 %0, %1, %2, %3;"
                            : "=l"(accA) : "l"(mm), "l"(sM64[idx]), "l"(accA));
                    }
                    cnt++;
                }
                idx++;
            }
        }
    }
    unsigned int za, wa, zb, wb;
    asm("mov.b64 {%0, %1}, %2;" : "=r"(za), "=r"(wa) : "l"(accA));
    asm("mov.b64 {%0, %1}, %2;" : "=r"(zb), "=r"(wb) : "l"(accB));
    Z = __uint_as_float(za) + __uint_as_float(zb);
    W = __uint_as_float(wa) + __uint_as_float(wb);
}

// ---------------- K3: entropy, 4 warps per 32-point group + last-block mean ----------------
#define ETPB 512            // 16 warps: 4 point-groups x 4 feature-subsets
__global__ void __launch_bounds__(ETPB)
entropy_kernel(const float* __restrict__ vel, float* __restrict__ out,
               int N, int nblk) {
    __shared__ float2 sM[NFP];
    __shared__ float2 zw[ETPB];
    __shared__ float  rs[4];
    __shared__ int    islast;
    int tid  = threadIdx.x;
    int lane = tid & 31;
    int warp = tid >> 5;
    int g    = warp >> 2;     // point-group 0..3
    int sub  = warp & 3;      // feature subset 0..3

    if (tid < NFP) sM[tid] = g_MZW[tid];
    __syncthreads();
    const unsigned long long* sM64 = reinterpret_cast<const unsigned long long*>(sM);

    int p = blockIdx.x * 128 + g * 32 + lane;
    float Z = 0.f, W = 0.f;
    if (p < N) {
        float x, y, z;
        load_unit(vel, p, x, y, z);
        float px[KDEG + 1], py[KDEG + 1], pz[KDEG + 1];
        px[0] = 1.0f; py[0] = 1.0f; pz[0] = 1.0f;
#pragma unroll
        for (int d = 1; d <= KDEG; d++) {
            px[d] = px[d - 1] * x;
            py[d] = py[d - 1] * y;
            pz[d] = pz[d - 1] * z;
        }
        switch (sub) {
            case 0: accum_zw<0>(sM64, px, py, pz, Z, W); break;
            case 1: accum_zw<1>(sM64, px, py, pz, Z, W); break;
            case 2: accum_zw<2>(sM64, px, py, pz, Z, W); break;
            default: accum_zw<3>(sM64, px, py, pz, Z, W); break;
        }
    }
    zw[tid] = make_float2(Z, W);
    __syncthreads();

    // threads 0..127 combine the 4 subsets of their point and finish it
    float H = 0.f;
    if (tid < 128) {
        int gg = tid >> 5, ll = tid & 31;
        float2 q0 = zw[(gg * 4 + 0) * 32 + ll];
        float2 q1 = zw[(gg * 4 + 1) * 32 + ll];
        float2 q2 = zw[(gg * 4 + 2) * 32 + ll];
        float2 q3 = zw[(gg * 4 + 3) * 32 + ll];
        float Zs = (q0.x + q1.x) + (q2.x + q3.x);
        float Ws = (q0.y + q1.y) + (q2.y + q3.y);
        int pp = blockIdx.x * 128 + tid;
        if (pp < N) H = logf(Zs) - Ws / Zs;
    }

    if (tid < 128) {
        H += __shfl_xor_sync(0xffffffffu, H, 16);
        H += __shfl_xor_sync(0xffffffffu, H, 8);
        H += __shfl_xor_sync(0xffffffffu, H, 4);
        H += __shfl_xor_sync(0xffffffffu, H, 2);
        H += __shfl_xor_sync(0xffffffffu, H, 1);
        if (lane == 0) rs[warp] = H;
    }
    __syncthreads();
    if (tid == 0) g_Hp[blockIdx.x] = rs[0] + rs[1] + rs[2] + rs[3];

    // ---- last-block mean ----
    __threadfence();
    if (tid == 0) islast = (atomicAdd(&g_t2, 1u) == (unsigned)(nblk - 1));
    __syncthreads();
    if (!islast) return;
    __threadfence();

    float a = 0.f;
    if (tid < 128) {
        for (int b = tid; b < nblk; b += 128) a += g_Hp[b];
        a += __shfl_xor_sync(0xffffffffu, a, 16);
        a += __shfl_xor_sync(0xffffffffu, a, 8);
        a += __shfl_xor_sync(0xffffffffu, a, 4);
        a += __shfl_xor_sync(0xffffffffu, a, 2);
        a += __shfl_xor_sync(0xffffffffu, a, 1);
        if (lane == 0) rs[warp] = a;
    }
    __syncthreads();
    if (tid == 0) {
        out[0] = (rs[0] + rs[1] + rs[2] + rs[3]) / (float)N - (float)N * 1e-8f;
        g_t2 = 0u;               // reset for next graph replay
    }
}

extern "C" void kernel_launch(void* const* d_in, const int* in_sizes, int n_in,
                              void* d_out, int out_size) {
    const float* vel = (const float*)d_in[0];   // velocities (N,3); positions unused
    int N = in_sizes[0] / 3;
    int nblk = (N + TPB - 1) / TPB;             // moments/entropy grid (128 pts/blk)
    if (nblk > MAXBLK) nblk = MAXBLK;
    if (nblk < 1) nblk = 1;

    moments_kernel<<<nblk, TPB>>>(vel, N, nblk);
    reduce_kernel<<<(NFP * 32 + 255) / 256, 256>>>(nblk);
    entropy_kernel<<<nblk, ETPB>>>(vel, (float*)d_out, N, nblk);
}